// round 1
// baseline (speedup 1.0000x reference)
#include <cuda_runtime.h>
#include <math.h>

#define C_   16
#define I_   64
#define H_   40
#define T_   512
#define G_   120
#define GP   128
#define BN   16
#define TCH  8
#define NTH  128

// shared memory layout (float offsets)
#define SM_WIH 0                          // [64][128]  W_ih transposed [k][g]
#define SM_WHH (SM_WIH + 64 * GP)         // [40][128]  W_hh transposed [k][g]
#define SM_BI  (SM_WHH + 40 * GP)         // [128]
#define SM_BH  (SM_BI + GP)               // [128]
#define SM_X   (SM_BH + GP)               // [8][64][16]  x chunk [tt][i][b]
#define SM_H   (SM_X + TCH * I_ * BN)     // [40][16]     hidden state [h][b]
#define SM_PI  (SM_H + H_ * BN)           // [16][132]    input-part preact [b][g] (pad 132)
#define SM_PH  (SM_PI + BN * 132)         // [16][132]    hidden-part preact
#define SM_TOT (SM_PH + BN * 132)         // = 26624 floats = 106496 bytes

__device__ __forceinline__ float sigf(float v) {
    return __fdividef(1.0f, 1.0f + __expf(-v));
}
__device__ __forceinline__ float tanh_fast(float a) {
    a = fminf(fmaxf(a, -15.0f), 15.0f);
    float e = __expf(2.0f * a);
    return __fdividef(e - 1.0f, e + 1.0f);
}

__global__ void __launch_bounds__(NTH, 2)
gru_fused_kernel(const float* __restrict__ x,
                 const float* __restrict__ Wih,
                 const float* __restrict__ Whh,
                 const float* __restrict__ bih,
                 const float* __restrict__ bhh,
                 const float* __restrict__ Wfc,
                 const float* __restrict__ bfc,
                 float* __restrict__ out)
{
    extern __shared__ float sm[];
    const int tid  = threadIdx.x;
    const int c    = blockIdx.x & 15;
    const int bblk = blockIdx.x >> 4;
    const int b0   = bblk * BN;

    // ---- stage weights transposed to [k][g] (g padded to 128 with zeros) ----
    for (int p = tid; p < 64 * GP; p += NTH) {
        int k = p >> 7, g = p & 127;
        sm[SM_WIH + p] = (g < G_) ? Wih[(c * G_ + g) * I_ + k] : 0.0f;
    }
    for (int p = tid; p < 40 * GP; p += NTH) {
        int k = p >> 7, g = p & 127;
        sm[SM_WHH + p] = (g < G_) ? Whh[(c * G_ + g) * H_ + k] : 0.0f;
    }
    if (tid < GP) {
        sm[SM_BI + tid] = (tid < G_) ? bih[c * G_ + tid] : 0.0f;
        sm[SM_BH + tid] = (tid < G_) ? bhh[c * G_ + tid] : 0.0f;
    }
    for (int p = tid; p < H_ * BN; p += NTH) sm[SM_H + p] = 0.0f;
    __syncthreads();

    const int lb  = tid & 15;   // staging: batch lane
    const int lig = tid >> 4;   // staging: i-group (0..7)
    const int gt  = tid & 31;   // compute: gate lane  (g = gt + 32*j)
    const int bt  = tid >> 5;   // compute: warp id -> batch group (b = 4*bt + i2)

    const float* xg = x + ((size_t)(b0 + lb) * C_ + c) * (size_t)(I_ * T_);

    for (int tc = 0; tc < T_; tc += TCH) {
        // ---- stage x chunk: x[b, c, i, tc..tc+7] -> sm_x[tt][i][b] ----
        #pragma unroll
        for (int r = 0; r < 8; ++r) {
            int i = lig + (r << 3);
            const float* gp = xg + i * T_ + tc;
            float4 v0 = *(const float4*)gp;
            float4 v1 = *(const float4*)(gp + 4);
            float* xp = sm + SM_X + i * 16 + lb;   // tt stride = 1024 floats
            xp[0]    = v0.x; xp[1024] = v0.y; xp[2048] = v0.z; xp[3072] = v0.w;
            xp[4096] = v1.x; xp[5120] = v1.y; xp[6144] = v1.z; xp[7168] = v1.w;
        }
        __syncthreads();

        for (int tt = 0; tt < TCH; ++tt) {
            float aI[4][4];   // [j = g-tile][i2 = b-tile]
            float aH[4][4];
            #pragma unroll
            for (int j = 0; j < 4; ++j)
                #pragma unroll
                for (int i2 = 0; i2 < 4; ++i2) { aI[j][i2] = 0.0f; aH[j][i2] = 0.0f; }

            // input projection part: K = 64 over x
            {
                const float* xrow = sm + SM_X + tt * 1024 + bt * 4;
                const float* wI   = sm + SM_WIH + gt;
                #pragma unroll 4
                for (int k = 0; k < I_; ++k) {
                    float4 xv = *(const float4*)(xrow + k * 16);
                    const float* wr = wI + k * GP;
                    float xa[4] = {xv.x, xv.y, xv.z, xv.w};
                    float wa[4] = {wr[0], wr[32], wr[64], wr[96]};
                    #pragma unroll
                    for (int j = 0; j < 4; ++j)
                        #pragma unroll
                        for (int i2 = 0; i2 < 4; ++i2)
                            aI[j][i2] += wa[j] * xa[i2];
                }
            }
            // hidden projection part: K = 40 over h
            {
                const float* hrow = sm + SM_H + bt * 4;
                const float* wH   = sm + SM_WHH + gt;
                #pragma unroll 4
                for (int k = 0; k < H_; ++k) {
                    float4 hv = *(const float4*)(hrow + k * 16);
                    const float* wr = wH + k * GP;
                    float ha[4] = {hv.x, hv.y, hv.z, hv.w};
                    float wa[4] = {wr[0], wr[32], wr[64], wr[96]};
                    #pragma unroll
                    for (int j = 0; j < 4; ++j)
                        #pragma unroll
                        for (int i2 = 0; i2 < 4; ++i2)
                            aH[j][i2] += wa[j] * ha[i2];
                }
            }

            // write pre-activations (+bias) to smem: pre[b][g], conflict-free (bank = gt)
            #pragma unroll
            for (int i2 = 0; i2 < 4; ++i2) {
                int b = bt * 4 + i2;
                float* pI = sm + SM_PI + b * 132 + gt;
                float* pH = sm + SM_PH + b * 132 + gt;
                #pragma unroll
                for (int j = 0; j < 4; ++j) {
                    pI[32 * j] = aI[j][i2] + sm[SM_BI + gt + 32 * j];
                    pH[32 * j] = aH[j][i2] + sm[SM_BH + gt + 32 * j];
                }
            }
            __syncthreads();

            // gate combine + h update: 640 (b,h) items over 128 threads
            #pragma unroll
            for (int q = 0; q < 5; ++q) {
                int p  = tid + q * NTH;
                int b  = p & 15;
                int hh = p >> 4;
                const float* pI = sm + SM_PI + b * 132;
                const float* pH = sm + SM_PH + b * 132;
                float rg = sigf(pI[hh]      + pH[hh]);
                float zg = sigf(pI[40 + hh] + pH[40 + hh]);
                float ng = tanh_fast(pI[80 + hh] + rg * pH[80 + hh]);
                float ho = sm[SM_H + hh * 16 + b];
                sm[SM_H + hh * 16 + b] = ng + zg * (ho - ng);   // (1-z)*n + z*h
            }
            __syncthreads();
        }
    }

    // ---- FC head: y[b,c] = sigmoid(h_final . W_fc[c] + b_fc[c]) ----
    if (tid < BN) {
        float acc = bfc[c];
        #pragma unroll
        for (int h2 = 0; h2 < H_; ++h2)
            acc += sm[SM_H + h2 * 16 + tid] * Wfc[c * H_ + h2];
        out[(size_t)(b0 + tid) * C_ + c] = sigf(acc);
    }
}

extern "C" void kernel_launch(void* const* d_in, const int* in_sizes, int n_in,
                              void* d_out, int out_size)
{
    const float* x   = (const float*)d_in[0];
    const float* Wih = (const float*)d_in[1];
    const float* Whh = (const float*)d_in[2];
    const float* bih = (const float*)d_in[3];
    const float* bhh = (const float*)d_in[4];
    const float* Wfc = (const float*)d_in[5];
    const float* bfc = (const float*)d_in[6];
    float* out = (float*)d_out;

    const int smem_bytes = SM_TOT * (int)sizeof(float);   // 106496
    cudaFuncSetAttribute(gru_fused_kernel,
                         cudaFuncAttributeMaxDynamicSharedMemorySize, smem_bytes);
    gru_fused_kernel<<<256, NTH, smem_bytes>>>(x, Wih, Whh, bih, bhh, Wfc, bfc, out);
}

// round 2
// speedup vs baseline: 1.2038x; 1.2038x over previous
#include <cuda_runtime.h>
#include <math.h>

#define C_   16
#define I_   64
#define H_   40
#define T_   512
#define G_   120
#define GP   128
#define BN   16
#define TCH  8
#define NTH  128
#define HS   20    // h row stride (floats): 16B-aligned rows, conflict-free updates

// shared layout (float offsets)
#define SM_WIH 0                          // [64][128]
#define SM_WHH (SM_WIH + I_ * GP)         // [40][128]
#define SM_X   (SM_WHH + H_ * GP)         // [8][64][16]
#define SM_H   (SM_X + TCH * I_ * BN)     // [40][HS]
#define SM_PI  (SM_H + H_ * HS)           // [16][132]
#define SM_PH  (SM_PI + BN * 132)         // [16][132]
#define SM_TOT (SM_PH + BN * 132)         // 26528 floats = 106112 B

typedef unsigned long long u64;

__device__ __forceinline__ u64 pack2(float lo, float hi) {
    u64 r;
    asm("mov.b64 %0, {%1, %2};"
        : "=l"(r) : "r"(__float_as_uint(lo)), "r"(__float_as_uint(hi)));
    return r;
}
__device__ __forceinline__ u64 dup2(float v) {
    u64 r;
    asm("mov.b64 %0, {%1, %1};" : "=l"(r) : "r"(__float_as_uint(v)));
    return r;
}
__device__ __forceinline__ u64 fma2(u64 a, u64 b, u64 c) {
    u64 d;
    asm("fma.rn.f32x2 %0, %1, %2, %3;" : "=l"(d) : "l"(a), "l"(b), "l"(c));
    return d;
}
__device__ __forceinline__ float sigf(float v) {
    return __fdividef(1.0f, 1.0f + __expf(-v));
}
__device__ __forceinline__ float tanh_fast(float a) {
    a = fminf(fmaxf(a, -15.0f), 15.0f);
    float e = __expf(2.0f * a);
    return __fdividef(e - 1.0f, e + 1.0f);
}

__global__ void __launch_bounds__(NTH, 2)
gru_fused2_kernel(const float* __restrict__ x,
                  const float* __restrict__ Wih,
                  const float* __restrict__ Whh,
                  const float* __restrict__ bih,
                  const float* __restrict__ bhh,
                  const float* __restrict__ Wfc,
                  const float* __restrict__ bfc,
                  float* __restrict__ out)
{
    extern __shared__ float sm[];
    const int tid  = threadIdx.x;
    const int c    = blockIdx.x & 15;
    const int b0   = (blockIdx.x >> 4) * BN;

    // ---- stage weights transposed to [k][g] (g zero-padded to 128) ----
    for (int p = tid; p < I_ * GP; p += NTH) {
        int k = p >> 7, g = p & 127;
        sm[SM_WIH + p] = (g < G_) ? Wih[(c * G_ + g) * I_ + k] : 0.0f;
    }
    for (int p = tid; p < H_ * GP; p += NTH) {
        int k = p >> 7, g = p & 127;
        sm[SM_WHH + p] = (g < G_) ? Whh[(c * G_ + g) * H_ + k] : 0.0f;
    }
    for (int p = tid; p < H_ * HS; p += NTH) sm[SM_H + p] = 0.0f;
    __syncthreads();

    const int gt = tid & 31;    // lane: g-pair index (g = 2*gt (+64))
    const int bt = tid >> 5;    // warp id -> owns batches bq..bq+3
    const int bq = bt * 4;

    // ---- bias pairs folded into accumulator init ----
    const int g0 = 2 * gt, g1 = 64 + 2 * gt;
    float bi1a = (g1     < G_) ? bih[c * G_ + g1]     : 0.0f;
    float bi1b = (g1 + 1 < G_) ? bih[c * G_ + g1 + 1] : 0.0f;
    float bh1a = (g1     < G_) ? bhh[c * G_ + g1]     : 0.0f;
    float bh1b = (g1 + 1 < G_) ? bhh[c * G_ + g1 + 1] : 0.0f;
    const u64 bI0 = pack2(bih[c * G_ + g0], bih[c * G_ + g0 + 1]);
    const u64 bI1 = pack2(bi1a, bi1b);
    const u64 bH0 = pack2(bhh[c * G_ + g0], bhh[c * G_ + g0 + 1]);
    const u64 bH1 = pack2(bh1a, bh1b);

    const int lb  = tid & 15;   // staging lanes
    const int lig = tid >> 4;
    const float* xg = x + ((size_t)(b0 + lb) * C_ + c) * (size_t)(I_ * T_);

    const float* wI   = sm + SM_WIH + 2 * gt;
    const float* wH   = sm + SM_WHH + 2 * gt;
    const float* hrow = sm + SM_H + bq;

    for (int tc = 0; tc < T_; tc += TCH) {
        __syncthreads();
        // ---- stage x chunk: x[b, c, i, tc..tc+7] -> sm_x[tt][i][b] ----
        #pragma unroll
        for (int r = 0; r < 8; ++r) {
            int i = lig + (r << 3);
            const float* gp = xg + i * T_ + tc;
            float4 v0 = *(const float4*)gp;
            float4 v1 = *(const float4*)(gp + 4);
            float* xp = sm + SM_X + i * 16 + lb;   // tt stride = 1024 floats
            xp[0]    = v0.x; xp[1024] = v0.y; xp[2048] = v0.z; xp[3072] = v0.w;
            xp[4096] = v1.x; xp[5120] = v1.y; xp[6144] = v1.z; xp[7168] = v1.w;
        }
        __syncthreads();

        for (int tt = 0; tt < TCH; ++tt) {
            u64 aI[2][4], aH[2][4];
            #pragma unroll
            for (int b = 0; b < 4; ++b) {
                aI[0][b] = bI0; aI[1][b] = bI1;
                aH[0][b] = bH0; aH[1][b] = bH1;
            }

            // ---- input projection: K = 64 ----
            {
                const float* xrow = sm + SM_X + tt * 1024 + bq;
                #pragma unroll 8
                for (int k = 0; k < I_; ++k) {
                    u64 w0 = *(const u64*)(wI + k * GP);
                    u64 w1 = *(const u64*)(wI + k * GP + 64);
                    float4 xv = *(const float4*)(xrow + k * 16);
                    u64 x0 = dup2(xv.x), x1 = dup2(xv.y);
                    u64 x2 = dup2(xv.z), x3 = dup2(xv.w);
                    aI[0][0] = fma2(w0, x0, aI[0][0]); aI[1][0] = fma2(w1, x0, aI[1][0]);
                    aI[0][1] = fma2(w0, x1, aI[0][1]); aI[1][1] = fma2(w1, x1, aI[1][1]);
                    aI[0][2] = fma2(w0, x2, aI[0][2]); aI[1][2] = fma2(w1, x2, aI[1][2]);
                    aI[0][3] = fma2(w0, x3, aI[0][3]); aI[1][3] = fma2(w1, x3, aI[1][3]);
                }
            }
            // ---- hidden projection: K = 40 ----
            {
                #pragma unroll 8
                for (int k = 0; k < H_; ++k) {
                    u64 w0 = *(const u64*)(wH + k * GP);
                    u64 w1 = *(const u64*)(wH + k * GP + 64);
                    float4 hv = *(const float4*)(hrow + k * HS);
                    u64 h0 = dup2(hv.x), h1 = dup2(hv.y);
                    u64 h2 = dup2(hv.z), h3 = dup2(hv.w);
                    aH[0][0] = fma2(w0, h0, aH[0][0]); aH[1][0] = fma2(w1, h0, aH[1][0]);
                    aH[0][1] = fma2(w0, h1, aH[0][1]); aH[1][1] = fma2(w1, h1, aH[1][1]);
                    aH[0][2] = fma2(w0, h2, aH[0][2]); aH[1][2] = fma2(w1, h2, aH[1][2]);
                    aH[0][3] = fma2(w0, h3, aH[0][3]); aH[1][3] = fma2(w1, h3, aH[1][3]);
                }
            }

            // ---- publish pre-activations (warp-private rows) ----
            #pragma unroll
            for (int b = 0; b < 4; ++b) {
                float* pI = sm + SM_PI + (bq + b) * 132 + 2 * gt;
                float* pH = sm + SM_PH + (bq + b) * 132 + 2 * gt;
                *(u64*)pI        = aI[0][b];
                *(u64*)(pI + 64) = aI[1][b];
                *(u64*)pH        = aH[0][b];
                *(u64*)(pH + 64) = aH[1][b];
            }
            __syncwarp();

            // ---- gate combine + h update (warp-local: 4 b x 40 h = 5/lane) ----
            {
                const int bl = bq + (gt >> 3);
                const int hb = gt & 7;
                const float* pI = sm + SM_PI + bl * 132;
                const float* pH = sm + SM_PH + bl * 132;
                #pragma unroll
                for (int q = 0; q < 5; ++q) {
                    int hh = hb + 8 * q;
                    float rg = sigf(pI[hh]      + pH[hh]);
                    float zg = sigf(pI[40 + hh] + pH[40 + hh]);
                    float ng = tanh_fast(pI[80 + hh] + rg * pH[80 + hh]);
                    float* hp = sm + SM_H + hh * HS + bl;
                    float ho = *hp;
                    *hp = ng + zg * (ho - ng);
                }
            }
            __syncwarp();
        }
    }

    __syncthreads();
    // ---- FC head: y[b,c] = sigmoid(h_final . W_fc[c] + b_fc[c]) ----
    if (tid < BN) {
        float acc = bfc[c];
        #pragma unroll
        for (int h2 = 0; h2 < H_; ++h2)
            acc += sm[SM_H + h2 * HS + tid] * Wfc[c * H_ + h2];
        out[(size_t)(b0 + tid) * C_ + c] = sigf(acc);
    }
}

extern "C" void kernel_launch(void* const* d_in, const int* in_sizes, int n_in,
                              void* d_out, int out_size)
{
    const float* x   = (const float*)d_in[0];
    const float* Wih = (const float*)d_in[1];
    const float* Whh = (const float*)d_in[2];
    const float* bih = (const float*)d_in[3];
    const float* bhh = (const float*)d_in[4];
    const float* Wfc = (const float*)d_in[5];
    const float* bfc = (const float*)d_in[6];
    float* out = (float*)d_out;

    const int smem_bytes = SM_TOT * (int)sizeof(float);   // 106112
    cudaFuncSetAttribute(gru_fused2_kernel,
                         cudaFuncAttributeMaxDynamicSharedMemorySize, smem_bytes);
    gru_fused2_kernel<<<256, NTH, smem_bytes>>>(x, Wih, Whh, bih, bhh, Wfc, bfc, out);
}